// round 16
// baseline (speedup 1.0000x reference)
#include <cuda_runtime.h>
#include <math.h>

// Problem constants
#define B    8
#define S    2048
#define D    1024
#define NB   20
#define NROW (B * NB)            // 160
#define NCTA 128
#define EPS  1e-8f
#define HB   (NROW * D)          // one h buffer
#define HD   (NROW * 2 * D)      // one hdup buffer

typedef unsigned long long ull;

// ---------------- static device scratch ----------------
__device__ float g_x   [B * S * D];        // x = e + m
__device__ float g_wx  [B * S * D];        // W @ x_t
__device__ float g_kx  [B * S * NB];       // keys @ x_t
__device__ float g_Ut  [D * D];            // U transposed
__device__ float g_KV  [NB * D];           // keys @ V^T
__device__ float g_hbuf[2 * NROW * D];     // unnormalized state, double-buffered
__device__ float g_hdup[2 * NROW * 2 * D]; // {h,h} dup pairs, double-buffered
__device__ float g_np  [2 * 16 * NROW];    // per-colgroup norm partials

__device__ unsigned g_bar_count = 0;
__device__ volatile unsigned g_bar_gen = 0;

// ---------------- helpers ----------------
__device__ __forceinline__ void fma2(ull& a, ull x, ull y) {
    asm("fma.rn.f32x2 %0, %1, %2, %0;" : "+l"(a) : "l"(x), "l"(y));
}
__device__ __forceinline__ float2 ull2f2(ull v) {
    float2 r;
    asm("mov.b64 {%0, %1}, %2;" : "=f"(r.x), "=f"(r.y) : "l"(v));
    return r;
}
__device__ __forceinline__ float ftanh(float v) {
    float e = __expf(2.f * v);
    return 1.f - __fdividef(2.f, e + 1.f);
}
__device__ __forceinline__ float fsigm(float v) {
    return __fdividef(1.f, 1.f + __expf(-v));
}

__device__ __forceinline__ void grid_barrier() {
    __threadfence();
    __syncthreads();
    if (threadIdx.x == 0) {
        unsigned g = g_bar_gen;
        if (atomicAdd(&g_bar_count, 1u) == NCTA - 1) {
            atomicExch(&g_bar_count, 0u);
            __threadfence();
            g_bar_gen = g + 1u;
        } else {
            while (g_bar_gen == g) { }
        }
    }
    __syncthreads();
}

// ---------------- launch 1: x = e + m, kx = keys @ x ----------------
__global__ __launch_bounds__(256) void k_prep_x(const float* __restrict__ e,
                                                const float* __restrict__ m,
                                                const float* __restrict__ keys) {
    int t = blockIdx.x, b = blockIdx.y;
    int tid = threadIdx.x;
    __shared__ float xs[D];
    int base = (b * S + t) * D;
    float4 ev = ((const float4*)(e + base))[tid];
    float4 mv = ((const float4*)(m + base))[tid];
    float4 xv;
    xv.x = ev.x + mv.x; xv.y = ev.y + mv.y;
    xv.z = ev.z + mv.z; xv.w = ev.w + mv.w;
    ((float4*)(g_x + base))[tid] = xv;
    ((float4*)xs)[tid] = xv;
    __syncthreads();
    int w = tid >> 5, l = tid & 31;
    for (int s2 = w; s2 < NB; s2 += 8) {
        const float* kr = keys + s2 * D;
        float a = 0.f;
        for (int i = l; i < D; i += 32) a += kr[i] * xs[i];
        #pragma unroll
        for (int o = 16; o; o >>= 1) a += __shfl_down_sync(0xffffffffu, a, o);
        if (l == 0) g_kx[(b * S + t) * NB + s2] = a;
    }
}

// ---------------- launch 2: fused setup (Ut transpose / KV / init) ----------
// blocks [0,1024): transpose U tile (32x32)
// blocks [1024,1184): KV[s][d0..d0+128) = keys[s] . V rows (direct)
// blocks [1184,1344): init h buffers + norm partial seed
__global__ __launch_bounds__(256) void k_setup(const float* __restrict__ U,
                                               const float* __restrict__ V,
                                               const float* __restrict__ keys,
                                               const float* __restrict__ state) {
    int bid = blockIdx.x;
    int tid = threadIdx.x;
    if (bid < 1024) {
        __shared__ float tile[32][33];
        int x0 = (bid & 31) * 32, y0 = (bid >> 5) * 32;
        int tx = tid & 31, ty = tid >> 5;
        #pragma unroll
        for (int i = 0; i < 32; i += 8)
            tile[ty + i][tx] = U[(y0 + ty + i) * D + x0 + tx];
        __syncthreads();
        #pragma unroll
        for (int i = 0; i < 32; i += 8)
            g_Ut[(x0 + ty + i) * D + y0 + tx] = tile[tx][ty + i];
    } else if (bid < 1184) {
        int idx = bid - 1024;
        int s = idx >> 3, d0 = (idx & 7) * 128;
        __shared__ float ks[D];
        ((float4*)ks)[tid] = ((const float4*)(keys + s * D))[tid];
        __syncthreads();
        int w = tid >> 5, l = tid & 31;
        for (int dd = w; dd < 128; dd += 8) {
            int d = d0 + dd;
            const float4* vr = (const float4*)(V + d * D);
            float a = 0.f;
            #pragma unroll
            for (int i = 0; i < 8; i++) {
                float4 v4 = vr[l + 32 * i];
                float4 k4 = ((const float4*)ks)[l + 32 * i];
                a += v4.x * k4.x + v4.y * k4.y + v4.z * k4.z + v4.w * k4.w;
            }
            #pragma unroll
            for (int o = 16; o; o >>= 1) a += __shfl_down_sync(0xffffffffu, a, o);
            if (l == 0) g_KV[s * D + d] = a;
        }
    } else {
        int idx = bid - 1184;
        int s = idx % NB, b = idx / NB;
        int row = b * NB + s;
        float4 v = ((const float4*)(state + s * D))[tid];
        ((float4*)(g_hbuf + row * D))[tid] = v;   // buffer 0
        float* dp = g_hdup + row * 2 * D + tid * 8;
        *(float4*)(dp)     = make_float4(v.x, v.x, v.y, v.y);
        *(float4*)(dp + 4) = make_float4(v.z, v.z, v.w, v.w);
        if (tid < 16) g_np[tid * NROW + row] = (tid == 0) ? 1.0f : 0.0f;
    }
}

// ---------------- launch 3: g_wx = X @ W^T  (16384x1024x1024) --------------
#define BM 64
#define BN 64
#define BK 32
#define PAD 4
__global__ __launch_bounds__(256) void k_wx_gemm(const float* __restrict__ W) {
    int n0 = blockIdx.x * BN;
    int m0 = blockIdx.y * BM;
    __shared__ float Xs[BK][BM + PAD];
    __shared__ float Ws[BK][BN + PAD];
    int tid = threadIdx.x;
    int tx = tid & 15, ty = tid >> 4;
    float acc[4][4];
    #pragma unroll
    for (int r = 0; r < 4; r++)
        #pragma unroll
        for (int c = 0; c < 4; c++) acc[r][c] = 0.f;

    for (int k0 = 0; k0 < D; k0 += BK) {
        #pragma unroll
        for (int i = 0; i < 2; i++) {
            int f = tid + i * 256;
            int r = f >> 3, kq = (f & 7) * 4;
            float4 xv = *(const float4*)(g_x + (m0 + r) * D + k0 + kq);
            Xs[kq + 0][r] = xv.x; Xs[kq + 1][r] = xv.y;
            Xs[kq + 2][r] = xv.z; Xs[kq + 3][r] = xv.w;
            float4 wv = *(const float4*)(W + (n0 + r) * D + k0 + kq);
            Ws[kq + 0][r] = wv.x; Ws[kq + 1][r] = wv.y;
            Ws[kq + 2][r] = wv.z; Ws[kq + 3][r] = wv.w;
        }
        __syncthreads();
        #pragma unroll
        for (int k = 0; k < BK; k++) {
            float4 a  = *(const float4*)&Xs[k][ty * 4];
            float4 bq = *(const float4*)&Ws[k][tx * 4];
            float ar[4] = {a.x, a.y, a.z, a.w};
            float br[4] = {bq.x, bq.y, bq.z, bq.w};
            #pragma unroll
            for (int r = 0; r < 4; r++)
                #pragma unroll
                for (int c = 0; c < 4; c++)
                    acc[r][c] = fmaf(ar[r], br[c], acc[r][c]);
        }
        __syncthreads();
    }
    #pragma unroll
    for (int r = 0; r < 4; r++) {
        float4 o = {acc[r][0], acc[r][1], acc[r][2], acc[r][3]};
        *(float4*)(g_wx + (m0 + ty * 4 + r) * D + n0 + tx * 4) = o;
    }
}

// ---------------- launch 4: persistent scan, ONE barrier per step ----------
// CTA = (cg 0..15 colgroup of 64, b 0..7). Deferred normalization:
// carry hn (unnorm) + inv = 1/(||hn||+eps); pre = inv*(hn@U^T)+KV+Wx,
// gate z = inv*(hn.x)+kx, hn' = inv*hn + g*tanh(pre). Norm partials per
// colgroup, summed at next step start. Double-buffered hn.
__global__ __launch_bounds__(256, 1) void k_scan(float* __restrict__ out) {
    const int tid = threadIdx.x;
    const int w = tid >> 5, l = tid & 31;
    const int hw = (tid >> 4) & 1, lh = tid & 15;
    const int cg = blockIdx.x & 15;
    const int b  = blockIdx.x >> 4;
    const int c0 = cg * 64;
    const int kbase = w * 128;

    __shared__ float4 s_red[8][20][16];   // 40 KB
    __shared__ float  x_s[D];             // 4 KB
    __shared__ float  s_inv[NB];
    __shared__ float  s_g[NB];

    for (int t = 0; t < S; t++) {
        const int rd = t & 1, wr = rd ^ 1;
        const float* hbuf_r = g_hbuf + rd * HB;
        const int tD = (b * S + t) * D;

        // A: inv from accumulated norm partials (prev step)
        if (tid < NB) {
            const float* np = g_np + rd * (16 * NROW) + (b * NB + tid);
            float ssum = 0.f;
            #pragma unroll
            for (int q = 0; q < 16; q++) ssum += np[q * NROW];
            s_inv[tid] = __fdividef(1.f, sqrtf(ssum) + EPS);
        }
        // B: stage x_t
        ((float4*)x_s)[tid] = ((const float4*)(g_x + tD))[tid];
        __syncthreads();

        // C: gate (full-row dot, per-warp rows)
        for (int j = w; j < NB; j += 8) {
            const float4* hr = (const float4*)(hbuf_r + (b * NB + j) * D);
            float a = 0.f;
            #pragma unroll
            for (int i = 0; i < 8; i++) {
                float4 h4 = hr[l + 32 * i];
                float4 x4 = ((const float4*)x_s)[l + 32 * i];
                a += h4.x * x4.x + h4.y * x4.y + h4.z * x4.z + h4.w * x4.w;
            }
            #pragma unroll
            for (int o = 16; o; o >>= 1) a += __shfl_down_sync(0xffffffffu, a, o);
            if (l == 0)
                s_g[j] = fsigm(s_inv[j] * a + g_kx[(b * S + t) * NB + j]);
        }

        // D: mainloop  acc[r][c-pair] += hn[r][k] * Ut[k][c]
        // warp = k-eighth (128 k), half-warp = 10 rows, lane = 4 cols
        ull acc0[10], acc1[10];
        #pragma unroll
        for (int j = 0; j < 10; j++) { acc0[j] = 0ull; acc1[j] = 0ull; }

        const float* hd = g_hdup + rd * HD + (b * NB + hw * 10) * (2 * D) + kbase * 2;
        const float* up = g_Ut + kbase * D + c0 + lh * 4;

        #pragma unroll 1
        for (int kk = 0; kk < 128; kk += 2) {
            ulonglong2 u0 = *(const ulonglong2*)(up + kk * D);
            ulonglong2 u1 = *(const ulonglong2*)(up + (kk + 1) * D);
            const float* hdk = hd + 2 * kk;
            #pragma unroll
            for (int j = 0; j < 10; j++) {
                ulonglong2 hh = *(const ulonglong2*)(hdk + j * (2 * D));
                fma2(acc0[j], hh.x, u0.x);
                fma2(acc1[j], hh.x, u0.y);
                fma2(acc0[j], hh.y, u1.x);
                fma2(acc1[j], hh.y, u1.y);
            }
        }

        // E: cross-warp k-reduction staging
        #pragma unroll
        for (int j = 0; j < 10; j++) {
            float2 a0 = ull2f2(acc0[j]);
            float2 a1 = ull2f2(acc1[j]);
            s_red[w][hw * 10 + j][lh] = make_float4(a0.x, a0.y, a1.x, a1.y);
        }
        __syncthreads();

        // F: epilogue — 320 units = 20 rows x 16 col-quads
        #pragma unroll
        for (int pass = 0; pass < 2; pass++) {
            if (pass == 1 && tid >= 64) break;
            int u = pass * 256 + tid;
            int row = u >> 4, lq = u & 15;
            int c = c0 + lq * 4;

            float4 s = s_red[0][row][lq];
            #pragma unroll
            for (int ww = 1; ww < 8; ww++) {
                float4 v = s_red[ww][row][lq];
                s.x += v.x; s.y += v.y; s.z += v.z; s.w += v.w;
            }
            float iv = s_inv[row], gg = s_g[row];
            float4 kv = *(const float4*)(g_KV + row * D + c);
            float4 wx = *(const float4*)(g_wx + tD + c);
            float4 hold = *(const float4*)(hbuf_r + (b * NB + row) * D + c);
            float4 hn;
            hn.x = iv * hold.x + gg * ftanh(iv * s.x + kv.x + wx.x);
            hn.y = iv * hold.y + gg * ftanh(iv * s.y + kv.y + wx.y);
            hn.z = iv * hold.z + gg * ftanh(iv * s.z + kv.z + wx.z);
            hn.w = iv * hold.w + gg * ftanh(iv * s.w + kv.w + wx.w);

            *(float4*)(g_hbuf + wr * HB + (b * NB + row) * D + c) = hn;
            float* dp = g_hdup + wr * HD + (b * NB + row) * (2 * D) + 2 * c;
            *(float4*)(dp)     = make_float4(hn.x, hn.x, hn.y, hn.y);
            *(float4*)(dp + 4) = make_float4(hn.z, hn.z, hn.w, hn.w);

            float pn = hn.x * hn.x + hn.y * hn.y + hn.z * hn.z + hn.w * hn.w;
            pn += __shfl_down_sync(0xffffffffu, pn, 8);
            pn += __shfl_down_sync(0xffffffffu, pn, 4);
            pn += __shfl_down_sync(0xffffffffu, pn, 2);
            pn += __shfl_down_sync(0xffffffffu, pn, 1);
            if ((tid & 15) == 0)
                g_np[wr * (16 * NROW) + cg * NROW + (b * NB + row)] = pn;
        }

        // G: one barrier per step
        grid_barrier();
    }

    // final: normalize buffer 0 (written at t=2047) into out
    if (tid < NB) {
        const float* np = g_np + (b * NB + tid);   // buffer 0
        float ssum = 0.f;
        #pragma unroll
        for (int q = 0; q < 16; q++) ssum += np[q * NROW];
        s_inv[tid] = __fdividef(1.f, sqrtf(ssum) + EPS);
    }
    __syncthreads();
    #pragma unroll
    for (int pass = 0; pass < 2; pass++) {
        if (pass == 1 && tid >= 64) break;
        int u = pass * 256 + tid;
        int row = u >> 4, lq = u & 15;
        int c = c0 + lq * 4;
        float4 h4 = *(const float4*)(g_hbuf + (b * NB + row) * D + c);
        float iv = s_inv[row];
        h4.x *= iv; h4.y *= iv; h4.z *= iv; h4.w *= iv;
        *(float4*)(out + (b * NB + row) * D + c) = h4;
    }
}

// ---------------- launch ----------------
extern "C" void kernel_launch(void* const* d_in, const int* in_sizes, int n_in,
                              void* d_out, int out_size) {
    const float* e     = (const float*)d_in[0];
    const float* m     = (const float*)d_in[1];
    const float* state = (const float*)d_in[2];
    const float* U     = (const float*)d_in[3];
    const float* V     = (const float*)d_in[4];
    const float* W     = (const float*)d_in[5];
    const float* keys  = (const float*)d_in[6];
    float* out = (float*)d_out;

    k_prep_x <<<dim3(S, B), 256>>>(e, m, keys);
    k_setup  <<<1344, 256>>>(U, V, keys, state);
    k_wx_gemm<<<dim3(D / BN, (B * S) / BM), 256>>>(W);
    k_scan   <<<NCTA, 256>>>(out);
}

// round 17
// speedup vs baseline: 1.4489x; 1.4489x over previous
#include <cuda_runtime.h>
#include <math.h>

// Problem constants
#define B    8
#define S    2048
#define D    1024
#define NB   20
#define NROW (B * NB)            // 160
#define NCTA 128
#define NT   512
#define EPS  1e-8f
#define HB   (NROW * D)          // one h buffer

typedef unsigned long long ull;

// ---------------- static device scratch ----------------
__device__ float g_x   [B * S * D];        // x = e + m
__device__ float g_wx  [B * S * D];        // W @ x_t
__device__ float g_kx  [B * S * NB];       // keys @ x_t
__device__ float g_Ut  [D * D];            // U transposed
__device__ float g_KV  [NB * D];           // keys @ V^T
__device__ float g_hbuf[2 * NROW * D];     // unnormalized state, double-buffered
__device__ float g_np  [2 * 16 * NROW];    // per-colgroup norm partials

__device__ unsigned g_bar_count = 0;
__device__ volatile unsigned g_bar_gen = 0;

// ---------------- helpers ----------------
__device__ __forceinline__ void fma2(ull& a, ull x, ull y) {
    asm("fma.rn.f32x2 %0, %1, %2, %0;" : "+l"(a) : "l"(x), "l"(y));
}
__device__ __forceinline__ ull dup2(float v) {
    ull r;
    asm("mov.b64 %0, {%1, %1};" : "=l"(r) : "f"(v));
    return r;
}
__device__ __forceinline__ float2 ull2f2(ull v) {
    float2 r;
    asm("mov.b64 {%0, %1}, %2;" : "=f"(r.x), "=f"(r.y) : "l"(v));
    return r;
}
__device__ __forceinline__ float ftanh(float v) {
    float e = __expf(2.f * v);
    return 1.f - __fdividef(2.f, e + 1.f);
}
__device__ __forceinline__ float fsigm(float v) {
    return __fdividef(1.f, 1.f + __expf(-v));
}

__device__ __forceinline__ void grid_barrier() {
    __threadfence();
    __syncthreads();
    if (threadIdx.x == 0) {
        unsigned g = g_bar_gen;
        if (atomicAdd(&g_bar_count, 1u) == NCTA - 1) {
            atomicExch(&g_bar_count, 0u);
            __threadfence();
            g_bar_gen = g + 1u;
        } else {
            while (g_bar_gen == g) { }
        }
    }
    __syncthreads();
}

// ---------------- launch 1: x = e + m, kx = keys @ x ----------------
__global__ __launch_bounds__(256) void k_prep_x(const float* __restrict__ e,
                                                const float* __restrict__ m,
                                                const float* __restrict__ keys) {
    int t = blockIdx.x, b = blockIdx.y;
    int tid = threadIdx.x;
    __shared__ float xs[D];
    int base = (b * S + t) * D;
    float4 ev = ((const float4*)(e + base))[tid];
    float4 mv = ((const float4*)(m + base))[tid];
    float4 xv;
    xv.x = ev.x + mv.x; xv.y = ev.y + mv.y;
    xv.z = ev.z + mv.z; xv.w = ev.w + mv.w;
    ((float4*)(g_x + base))[tid] = xv;
    ((float4*)xs)[tid] = xv;
    __syncthreads();
    int w = tid >> 5, l = tid & 31;
    for (int s2 = w; s2 < NB; s2 += 8) {
        const float* kr = keys + s2 * D;
        float a = 0.f;
        for (int i = l; i < D; i += 32) a += kr[i] * xs[i];
        #pragma unroll
        for (int o = 16; o; o >>= 1) a += __shfl_down_sync(0xffffffffu, a, o);
        if (l == 0) g_kx[(b * S + t) * NB + s2] = a;
    }
}

// ---------------- launch 2: fused setup (Ut transpose / KV / init) ----------
__global__ __launch_bounds__(256) void k_setup(const float* __restrict__ U,
                                               const float* __restrict__ V,
                                               const float* __restrict__ keys,
                                               const float* __restrict__ state) {
    int bid = blockIdx.x;
    int tid = threadIdx.x;
    if (bid < 1024) {
        __shared__ float tile[32][33];
        int x0 = (bid & 31) * 32, y0 = (bid >> 5) * 32;
        int tx = tid & 31, ty = tid >> 5;
        #pragma unroll
        for (int i = 0; i < 32; i += 8)
            tile[ty + i][tx] = U[(y0 + ty + i) * D + x0 + tx];
        __syncthreads();
        #pragma unroll
        for (int i = 0; i < 32; i += 8)
            g_Ut[(x0 + ty + i) * D + y0 + tx] = tile[tx][ty + i];
    } else if (bid < 1184) {
        int idx = bid - 1024;
        int s = idx >> 3, d0 = (idx & 7) * 128;
        __shared__ float ks[D];
        ((float4*)ks)[tid] = ((const float4*)(keys + s * D))[tid];
        __syncthreads();
        int w = tid >> 5, l = tid & 31;
        for (int dd = w; dd < 128; dd += 8) {
            int d = d0 + dd;
            const float4* vr = (const float4*)(V + d * D);
            float a = 0.f;
            #pragma unroll
            for (int i = 0; i < 8; i++) {
                float4 v4 = vr[l + 32 * i];
                float4 k4 = ((const float4*)ks)[l + 32 * i];
                a += v4.x * k4.x + v4.y * k4.y + v4.z * k4.z + v4.w * k4.w;
            }
            #pragma unroll
            for (int o = 16; o; o >>= 1) a += __shfl_down_sync(0xffffffffu, a, o);
            if (l == 0) g_KV[s * D + d] = a;
        }
    } else {
        int idx = bid - 1184;
        int s = idx % NB, b = idx / NB;
        int row = b * NB + s;
        float4 v = ((const float4*)(state + s * D))[tid];
        ((float4*)(g_hbuf + row * D))[tid] = v;   // buffer 0
        if (tid < 16) g_np[tid * NROW + row] = (tid == 0) ? 1.0f : 0.0f;
    }
}

// ---------------- launch 3: g_wx = X @ W^T ----------------
#define BM 64
#define BN 64
#define BK 32
#define PAD 4
__global__ __launch_bounds__(256) void k_wx_gemm(const float* __restrict__ W) {
    int n0 = blockIdx.x * BN;
    int m0 = blockIdx.y * BM;
    __shared__ float Xs[BK][BM + PAD];
    __shared__ float Ws[BK][BN + PAD];
    int tid = threadIdx.x;
    int tx = tid & 15, ty = tid >> 4;
    float acc[4][4];
    #pragma unroll
    for (int r = 0; r < 4; r++)
        #pragma unroll
        for (int c = 0; c < 4; c++) acc[r][c] = 0.f;

    for (int k0 = 0; k0 < D; k0 += BK) {
        #pragma unroll
        for (int i = 0; i < 2; i++) {
            int f = tid + i * 256;
            int r = f >> 3, kq = (f & 7) * 4;
            float4 xv = *(const float4*)(g_x + (m0 + r) * D + k0 + kq);
            Xs[kq + 0][r] = xv.x; Xs[kq + 1][r] = xv.y;
            Xs[kq + 2][r] = xv.z; Xs[kq + 3][r] = xv.w;
            float4 wv = *(const float4*)(W + (n0 + r) * D + k0 + kq);
            Ws[kq + 0][r] = wv.x; Ws[kq + 1][r] = wv.y;
            Ws[kq + 2][r] = wv.z; Ws[kq + 3][r] = wv.w;
        }
        __syncthreads();
        #pragma unroll
        for (int k = 0; k < BK; k++) {
            float4 a  = *(const float4*)&Xs[k][ty * 4];
            float4 bq = *(const float4*)&Ws[k][tx * 4];
            float ar[4] = {a.x, a.y, a.z, a.w};
            float br[4] = {bq.x, bq.y, bq.z, bq.w};
            #pragma unroll
            for (int r = 0; r < 4; r++)
                #pragma unroll
                for (int c = 0; c < 4; c++)
                    acc[r][c] = fmaf(ar[r], br[c], acc[r][c]);
        }
        __syncthreads();
    }
    #pragma unroll
    for (int r = 0; r < 4; r++) {
        float4 o = {acc[r][0], acc[r][1], acc[r][2], acc[r][3]};
        *(float4*)(g_wx + (m0 + ty * 4 + r) * D + n0 + tx * 4) = o;
    }
}

// ---------------- launch 4: persistent scan ----------------
// 128 CTAs x 512 threads (16 warps/SM, occ 25%). One barrier per step,
// deferred L2-normalization (carry unnormalized hn + scalar inv).
// CTA = (cg 0..15: 64 cols, b 0..7).
// Warp w: k-slice ks=w&7 (128 k), row-decade rg=w>>3; half-warp = 5 rows.
// Lane lh=l&15: 4 cols. h loaded raw (4 k per LDG.128), dup-packed in regs.
__global__ __launch_bounds__(NT, 1) void k_scan(float* __restrict__ out) {
    const int tid = threadIdx.x;
    const int w = tid >> 5, l = tid & 31;
    const int hw = (l >> 4), lh = l & 15;
    const int ks = w & 7, rg = w >> 3;
    const int cg = blockIdx.x & 15;
    const int b  = blockIdx.x >> 4;
    const int c0 = cg * 64;
    const int k0 = ks * 128;
    const int r0 = rg * 10 + hw * 5;       // first of 5 rows

    __shared__ float4 s_red[8][20][16];    // 40 KB
    __shared__ float  x_s[D];              // 4 KB
    __shared__ float  s_inv[NB];
    __shared__ float  s_g[NB];

    const float* up = g_Ut + k0 * D + c0 + lh * 4;

    for (int t = 0; t < S; t++) {
        const int rd = t & 1, wr = rd ^ 1;
        const float* hbuf_r = g_hbuf + rd * HB;
        const int tD = (b * S + t) * D;

        // A: inv from accumulated norm partials
        if (tid < NB) {
            const float* np = g_np + rd * (16 * NROW) + (b * NB + tid);
            float ssum = 0.f;
            #pragma unroll
            for (int q = 0; q < 16; q++) ssum += np[q * NROW];
            s_inv[tid] = __fdividef(1.f, sqrtf(ssum) + EPS);
        }
        // B: stage x_t
        if (tid < 256) ((float4*)x_s)[tid] = ((const float4*)(g_x + tD))[tid];
        __syncthreads();

        // C: gate
        for (int j = w; j < NB; j += 16) {
            const float4* hr = (const float4*)(hbuf_r + (b * NB + j) * D);
            float a = 0.f;
            #pragma unroll
            for (int i = 0; i < 8; i++) {
                float4 h4 = hr[l + 32 * i];
                float4 x4 = ((const float4*)x_s)[l + 32 * i];
                a += h4.x * x4.x + h4.y * x4.y + h4.z * x4.z + h4.w * x4.w;
            }
            #pragma unroll
            for (int o = 16; o; o >>= 1) a += __shfl_down_sync(0xffffffffu, a, o);
            if (l == 0)
                s_g[j] = fsigm(s_inv[j] * a + g_kx[(b * S + t) * NB + j]);
        }

        // D: mainloop  acc[5 rows][4 cols] += hn[row][k] * Ut[k][c]
        ull acc0[5], acc1[5];
        #pragma unroll
        for (int j = 0; j < 5; j++) { acc0[j] = 0ull; acc1[j] = 0ull; }

        const float* hb = hbuf_r + (b * NB + r0) * D + k0;

        #pragma unroll 1
        for (int kk = 0; kk < 128; kk += 4) {
            ulonglong2 u0 = *(const ulonglong2*)(up + (kk + 0) * D);
            ulonglong2 u1 = *(const ulonglong2*)(up + (kk + 1) * D);
            ulonglong2 u2 = *(const ulonglong2*)(up + (kk + 2) * D);
            ulonglong2 u3 = *(const ulonglong2*)(up + (kk + 3) * D);
            #pragma unroll
            for (int j = 0; j < 5; j++) {
                float4 h4 = *(const float4*)(hb + j * D + kk);
                ull hx = dup2(h4.x), hy = dup2(h4.y);
                ull hz = dup2(h4.z), hwv = dup2(h4.w);
                fma2(acc0[j], hx, u0.x);  fma2(acc1[j], hx, u0.y);
                fma2(acc0[j], hy, u1.x);  fma2(acc1[j], hy, u1.y);
                fma2(acc0[j], hz, u2.x);  fma2(acc1[j], hz, u2.y);
                fma2(acc0[j], hwv, u3.x); fma2(acc1[j], hwv, u3.y);
            }
        }

        // E: stage k-slice partials
        #pragma unroll
        for (int j = 0; j < 5; j++) {
            float2 a0 = ull2f2(acc0[j]);
            float2 a1 = ull2f2(acc1[j]);
            s_red[ks][r0 + j][lh] = make_float4(a0.x, a0.y, a1.x, a1.y);
        }
        __syncthreads();

        // F: epilogue — 320 units = 20 rows x 16 col-quads
        if (tid < 320) {
            int row = tid >> 4, lq = tid & 15;
            int c = c0 + lq * 4;

            float4 s = s_red[0][row][lq];
            #pragma unroll
            for (int ww = 1; ww < 8; ww++) {
                float4 v = s_red[ww][row][lq];
                s.x += v.x; s.y += v.y; s.z += v.z; s.w += v.w;
            }
            float iv = s_inv[row], gg = s_g[row];
            float4 kv = *(const float4*)(g_KV + row * D + c);
            float4 wx = *(const float4*)(g_wx + tD + c);
            float4 hold = *(const float4*)(hbuf_r + (b * NB + row) * D + c);
            float4 hn;
            hn.x = iv * hold.x + gg * ftanh(iv * s.x + kv.x + wx.x);
            hn.y = iv * hold.y + gg * ftanh(iv * s.y + kv.y + wx.y);
            hn.z = iv * hold.z + gg * ftanh(iv * s.z + kv.z + wx.z);
            hn.w = iv * hold.w + gg * ftanh(iv * s.w + kv.w + wx.w);

            *(float4*)(g_hbuf + wr * HB + (b * NB + row) * D + c) = hn;

            float pn = hn.x * hn.x + hn.y * hn.y + hn.z * hn.z + hn.w * hn.w;
            pn += __shfl_down_sync(0xffffffffu, pn, 8);
            pn += __shfl_down_sync(0xffffffffu, pn, 4);
            pn += __shfl_down_sync(0xffffffffu, pn, 2);
            pn += __shfl_down_sync(0xffffffffu, pn, 1);
            if (lq == 0)
                g_np[wr * (16 * NROW) + cg * NROW + (b * NB + row)] = pn;
        }

        // G: one barrier per step
        grid_barrier();
    }

    // final: normalize buffer 0 (state after t=2047) into out
    if (tid < NB) {
        const float* np = g_np + (b * NB + tid);
        float ssum = 0.f;
        #pragma unroll
        for (int q = 0; q < 16; q++) ssum += np[q * NROW];
        s_inv[tid] = __fdividef(1.f, sqrtf(ssum) + EPS);
    }
    __syncthreads();
    if (tid < 320) {
        int row = tid >> 4, lq = tid & 15;
        int c = c0 + lq * 4;
        float4 h4 = *(const float4*)(g_hbuf + (b * NB + row) * D + c);
        float iv = s_inv[row];
        h4.x *= iv; h4.y *= iv; h4.z *= iv; h4.w *= iv;
        *(float4*)(out + (b * NB + row) * D + c) = h4;
    }
}

// ---------------- launch ----------------
extern "C" void kernel_launch(void* const* d_in, const int* in_sizes, int n_in,
                              void* d_out, int out_size) {
    const float* e     = (const float*)d_in[0];
    const float* m     = (const float*)d_in[1];
    const float* state = (const float*)d_in[2];
    const float* U     = (const float*)d_in[3];
    const float* V     = (const float*)d_in[4];
    const float* W     = (const float*)d_in[5];
    const float* keys  = (const float*)d_in[6];
    float* out = (float*)d_out;

    k_prep_x <<<dim3(S, B), 256>>>(e, m, keys);
    k_setup  <<<1344, 256>>>(U, V, keys, state);
    k_wx_gemm<<<dim3(D / BN, (B * S) / BM), 256>>>(W);
    k_scan   <<<NCTA, NT>>>(out);
}